// round 2
// baseline (speedup 1.0000x reference)
#include <cuda_runtime.h>
#include <math.h>

#define N_NODES  50000
#define N_EDGES  800000
#define F_DIM    64
#define L_DIM    1024
#define R_ROUNDS 3
#define N_CLASS  10

// Scratch (device globals — no allocation allowed)
__device__ float g_e[N_NODES * F_DIM];   // current embeddings (r after gemm1)
__device__ float g_v[N_NODES * F_DIM];   // v = e + scatter-sum
__device__ float g_f[L_DIM];             // fingerprint accumulator

__device__ __forceinline__ void red_add_v4(float* p, float4 v) {
    asm volatile("red.global.add.v4.f32 [%0], {%1,%2,%3,%4};"
                 :: "l"(p), "f"(v.x), "f"(v.y), "f"(v.z), "f"(v.w) : "memory");
}

// e = emb[node_feature]; v = e; f = 0
__global__ void gather_init(const int* __restrict__ nf, const float* __restrict__ emb) {
    int tid = blockIdx.x * blockDim.x + threadIdx.x;
    if (tid < L_DIM) g_f[tid] = 0.0f;
    if (tid >= N_NODES * 16) return;
    int node = tid >> 4;
    int c    = tid & 15;
    int ft = nf[node];
    float4 val = ((const float4*)emb)[ft * 16 + c];
    ((float4*)g_e)[node * 16 + c] = val;
    ((float4*)g_v)[node * 16 + c] = val;
}

// v[dst] += e[src] for every edge (vector atomics, 16 threads/edge)
__global__ void scatter_kernel(const int* __restrict__ src, const int* __restrict__ dst) {
    int tid = blockIdx.x * blockDim.x + threadIdx.x;
    if (tid >= N_EDGES * 16) return;
    int e = tid >> 4;
    int c = tid & 15;
    int s = __ldg(src + e);
    int d = __ldg(dst + e);
    float4 val = ((const float4*)g_e)[s * 16 + c];
    red_add_v4(g_v + d * 64 + c * 4, val);
}

// r = relu(v @ Wh[l] + bh[l]); write r into BOTH g_e and g_v (v-init for next round)
__global__ void __launch_bounds__(256) gemm1_kernel(const float* __restrict__ Wh,
                                                    const float* __restrict__ bh, int l) {
    __shared__ float Whs[F_DIM * F_DIM];
    __shared__ float bhs[F_DIM];
    int t = threadIdx.x;
    {
        const float4* W4 = (const float4*)(Wh + l * F_DIM * F_DIM);
        float4* Ws4 = (float4*)Whs;
        for (int i = t; i < F_DIM * F_DIM / 4; i += 256) Ws4[i] = W4[i];
        if (t < F_DIM) bhs[t] = bh[l * F_DIM + t];
    }
    __syncthreads();
    int node = blockIdx.x * 256 + t;
    if (node >= N_NODES) return;

    float acc[F_DIM];
#pragma unroll
    for (int j = 0; j < F_DIM; j++) acc[j] = bhs[j];

    const float4* v4 = ((const float4*)g_v) + node * 16;
#pragma unroll
    for (int k4 = 0; k4 < 16; k4++) {
        float4 vv = v4[k4];
#pragma unroll
        for (int j = 0; j < F_DIM; j++) {
            acc[j] += vv.x * Whs[(k4 * 4 + 0) * F_DIM + j];
            acc[j] += vv.y * Whs[(k4 * 4 + 1) * F_DIM + j];
            acc[j] += vv.z * Whs[(k4 * 4 + 2) * F_DIM + j];
            acc[j] += vv.w * Whs[(k4 * 4 + 3) * F_DIM + j];
        }
    }
    float4* e4 = ((float4*)g_e) + node * 16;
    float4* w4 = ((float4*)g_v) + node * 16;
#pragma unroll
    for (int j4 = 0; j4 < 16; j4++) {
        float4 o;
        o.x = fmaxf(acc[j4 * 4 + 0], 0.0f);
        o.y = fmaxf(acc[j4 * 4 + 1], 0.0f);
        o.z = fmaxf(acc[j4 * 4 + 2], 0.0f);
        o.w = fmaxf(acc[j4 * 4 + 3], 0.0f);
        e4[j4] = o;
        w4[j4] = o;
    }
}

// Fused: logits = r @ Wo[l] + bo[l]; softmax per node; accumulate into g_f.
// 512 threads = 16 warps = 16 nodes per block. Each warp holds 1024 logits in
// 8xfloat4 per lane (bin = g*128 + lane*4 + c). Wo streamed via smem in 16-row chunks.
__global__ void __launch_bounds__(512) fused_kernel(const float* __restrict__ Wo,
                                                    const float* __restrict__ bo, int l) {
    __shared__ float Wos[16 * L_DIM];   // 64 KB
    __shared__ float rs[16 * F_DIM];    // 4 KB
    __shared__ float fpart[L_DIM];      // 4 KB

    int t = threadIdx.x;
    int w = t >> 5;
    int lane = t & 31;
    int nodeBase = blockIdx.x * 16;

    for (int i = t; i < L_DIM; i += 512) fpart[i] = 0.0f;
    {
        const float4* e4 = (const float4*)g_e;
        float4* rs4 = (float4*)rs;
        if (t < 256) rs4[t] = e4[nodeBase * 16 + t];
    }

    float4 acc[8];
    {
        const float4* bo4 = (const float4*)(bo + l * L_DIM);
#pragma unroll
        for (int g = 0; g < 8; g++) acc[g] = bo4[g * 32 + lane];
    }

    const float4* Wo4 = (const float4*)(Wo + l * F_DIM * L_DIM);
    float4* Wos4 = (float4*)Wos;

    for (int kc = 0; kc < 4; kc++) {
        __syncthreads();
        for (int i = t; i < 4096; i += 512) Wos4[i] = Wo4[kc * 4096 + i];
        __syncthreads();
#pragma unroll
        for (int kk = 0; kk < 16; kk++) {
            float rk = rs[w * F_DIM + kc * 16 + kk];
#pragma unroll
            for (int g = 0; g < 8; g++) {
                float4 wv = Wos4[kk * 256 + g * 32 + lane];
                acc[g].x += rk * wv.x;
                acc[g].y += rk * wv.y;
                acc[g].z += rk * wv.z;
                acc[g].w += rk * wv.w;
            }
        }
    }

    // per-node (per-warp) softmax over the 1024 logits
    float mx = -1e30f;
#pragma unroll
    for (int g = 0; g < 8; g++)
        mx = fmaxf(mx, fmaxf(fmaxf(acc[g].x, acc[g].y), fmaxf(acc[g].z, acc[g].w)));
#pragma unroll
    for (int off = 16; off; off >>= 1)
        mx = fmaxf(mx, __shfl_xor_sync(0xffffffffu, mx, off));

    float sum = 0.0f;
#pragma unroll
    for (int g = 0; g < 8; g++) {
        acc[g].x = __expf(acc[g].x - mx); sum += acc[g].x;
        acc[g].y = __expf(acc[g].y - mx); sum += acc[g].y;
        acc[g].z = __expf(acc[g].z - mx); sum += acc[g].z;
        acc[g].w = __expf(acc[g].w - mx); sum += acc[g].w;
    }
#pragma unroll
    for (int off = 16; off; off >>= 1)
        sum += __shfl_xor_sync(0xffffffffu, sum, off);
    float inv = 1.0f / sum;

#pragma unroll
    for (int g = 0; g < 8; g++) {
        int base = g * 128 + lane * 4;
        atomicAdd(&fpart[base + 0], acc[g].x * inv);
        atomicAdd(&fpart[base + 1], acc[g].y * inv);
        atomicAdd(&fpart[base + 2], acc[g].z * inv);
        atomicAdd(&fpart[base + 3], acc[g].w * inv);
    }
    __syncthreads();
    if (t < 256) red_add_v4(g_f + t * 4, ((float4*)fpart)[t]);
}

// out = log_softmax(f @ Wcl + bcl)
__global__ void classify_kernel(const float* __restrict__ Wcl,
                                const float* __restrict__ bcl, float* __restrict__ out) {
    int t = threadIdx.x;
    int lane = t & 31, w = t >> 5;
    float loc[N_CLASS];
#pragma unroll
    for (int c = 0; c < N_CLASS; c++) loc[c] = 0.0f;
    for (int i = t; i < L_DIM; i += 256) {
        float fv = g_f[i];
#pragma unroll
        for (int c = 0; c < N_CLASS; c++) loc[c] += fv * Wcl[i * N_CLASS + c];
    }
#pragma unroll
    for (int c = 0; c < N_CLASS; c++)
#pragma unroll
        for (int off = 16; off; off >>= 1)
            loc[c] += __shfl_xor_sync(0xffffffffu, loc[c], off);

    __shared__ float ws[8][N_CLASS];
    if (lane == 0)
#pragma unroll
        for (int c = 0; c < N_CLASS; c++) ws[w][c] = loc[c];
    __syncthreads();
    if (t == 0) {
        float z[N_CLASS];
#pragma unroll
        for (int c = 0; c < N_CLASS; c++) {
            z[c] = bcl[c];
            for (int k = 0; k < 8; k++) z[c] += ws[k][c];
        }
        float m = z[0];
#pragma unroll
        for (int c = 1; c < N_CLASS; c++) m = fmaxf(m, z[c]);
        float s = 0.0f;
#pragma unroll
        for (int c = 0; c < N_CLASS; c++) s += __expf(z[c] - m);
        float ls = logf(s);
#pragma unroll
        for (int c = 0; c < N_CLASS; c++) out[c] = z[c] - m - ls;
    }
}

extern "C" void kernel_launch(void* const* d_in, const int* in_sizes, int n_in,
                              void* d_out, int out_size) {
    const int*   nf   = (const int*)  d_in[0];
    const int*   esrc = (const int*)  d_in[1];
    const int*   edst = (const int*)  d_in[2];
    const float* emb  = (const float*)d_in[3];
    const float* Wh   = (const float*)d_in[4];
    const float* bh   = (const float*)d_in[5];
    const float* Wo   = (const float*)d_in[6];
    const float* bo   = (const float*)d_in[7];
    const float* Wcl  = (const float*)d_in[8];
    const float* bcl  = (const float*)d_in[9];
    float* out = (float*)d_out;

    gather_init<<<(N_NODES * 16 + 255) / 256, 256>>>(nf, emb);
    for (int l = 0; l < R_ROUNDS; l++) {
        scatter_kernel<<<(N_EDGES * 16 + 255) / 256, 256>>>(esrc, edst);
        gemm1_kernel<<<(N_NODES + 255) / 256, 256>>>(Wh, bh, l);
        fused_kernel<<<N_NODES / 16, 512>>>(Wo, bo, l);
    }
    classify_kernel<<<1, 256>>>(Wcl, bcl, out);
}

// round 3
// speedup vs baseline: 2.2963x; 2.2963x over previous
#include <cuda_runtime.h>
#include <math.h>

#define N_NODES  50000
#define N_EDGES  800000
#define F_DIM    64
#define L_DIM    1024
#define R_ROUNDS 3
#define N_CLASS  10

#define NPW      4            // nodes per warp in fused kernel
#define FB_THREADS 384        // 12 warps
#define NPB      (12 * NPW)   // 48 nodes per block

// Scratch (device globals — no allocation allowed)
__device__ float g_e[N_NODES * F_DIM];   // current embeddings (r after gemm1)
__device__ float g_v[N_NODES * F_DIM];   // v = e + scatter-sum
__device__ float g_f[L_DIM];             // fingerprint accumulator

__device__ __forceinline__ void red_add_v4(float* p, float4 v) {
    asm volatile("red.global.add.v4.f32 [%0], {%1,%2,%3,%4};"
                 :: "l"(p), "f"(v.x), "f"(v.y), "f"(v.z), "f"(v.w) : "memory");
}

__device__ __forceinline__ unsigned long long pack2(float a, float b) {
    unsigned long long r;
    asm("mov.b64 %0, {%1,%2};" : "=l"(r) : "f"(a), "f"(b));
    return r;
}
__device__ __forceinline__ void unpack2(unsigned long long v, float& a, float& b) {
    asm("mov.b64 {%0,%1}, %2;" : "=f"(a), "=f"(b) : "l"(v));
}
__device__ __forceinline__ void fma2(unsigned long long& d,
                                     unsigned long long a, unsigned long long b) {
    asm("fma.rn.f32x2 %0, %1, %2, %0;" : "+l"(d) : "l"(a), "l"(b));
}

// e = emb[node_feature]; v = e; f = 0
__global__ void gather_init(const int* __restrict__ nf, const float* __restrict__ emb) {
    int tid = blockIdx.x * blockDim.x + threadIdx.x;
    if (tid < L_DIM) g_f[tid] = 0.0f;
    if (tid >= N_NODES * 16) return;
    int node = tid >> 4;
    int c    = tid & 15;
    int ft = nf[node];
    float4 val = ((const float4*)emb)[ft * 16 + c];
    ((float4*)g_e)[node * 16 + c] = val;
    ((float4*)g_v)[node * 16 + c] = val;
}

// v[dst] += e[src] for every edge (vector atomics, 16 threads/edge)
__global__ void scatter_kernel(const int* __restrict__ src, const int* __restrict__ dst) {
    int tid = blockIdx.x * blockDim.x + threadIdx.x;
    if (tid >= N_EDGES * 16) return;
    int e = tid >> 4;
    int c = tid & 15;
    int s = __ldg(src + e);
    int d = __ldg(dst + e);
    float4 val = ((const float4*)g_e)[s * 16 + c];
    red_add_v4(g_v + d * 64 + c * 4, val);
}

// r = relu(v @ Wh[l] + bh[l]); write r into BOTH g_e and g_v (v-init for next round)
__global__ void __launch_bounds__(256) gemm1_kernel(const float* __restrict__ Wh,
                                                    const float* __restrict__ bh, int l) {
    __shared__ float Whs[F_DIM * F_DIM];
    __shared__ float bhs[F_DIM];
    int t = threadIdx.x;
    {
        const float4* W4 = (const float4*)(Wh + l * F_DIM * F_DIM);
        float4* Ws4 = (float4*)Whs;
        for (int i = t; i < F_DIM * F_DIM / 4; i += 256) Ws4[i] = W4[i];
        if (t < F_DIM) bhs[t] = bh[l * F_DIM + t];
    }
    __syncthreads();
    int node = blockIdx.x * 256 + t;
    if (node >= N_NODES) return;

    float acc[F_DIM];
#pragma unroll
    for (int j = 0; j < F_DIM; j++) acc[j] = bhs[j];

    const float4* v4 = ((const float4*)g_v) + node * 16;
#pragma unroll
    for (int k4 = 0; k4 < 16; k4++) {
        float4 vv = v4[k4];
#pragma unroll
        for (int j = 0; j < F_DIM; j++) {
            acc[j] += vv.x * Whs[(k4 * 4 + 0) * F_DIM + j];
            acc[j] += vv.y * Whs[(k4 * 4 + 1) * F_DIM + j];
            acc[j] += vv.z * Whs[(k4 * 4 + 2) * F_DIM + j];
            acc[j] += vv.w * Whs[(k4 * 4 + 3) * F_DIM + j];
        }
    }
    float4* e4 = ((float4*)g_e) + node * 16;
    float4* w4 = ((float4*)g_v) + node * 16;
#pragma unroll
    for (int j4 = 0; j4 < 16; j4++) {
        float4 o;
        o.x = fmaxf(acc[j4 * 4 + 0], 0.0f);
        o.y = fmaxf(acc[j4 * 4 + 1], 0.0f);
        o.z = fmaxf(acc[j4 * 4 + 2], 0.0f);
        o.w = fmaxf(acc[j4 * 4 + 3], 0.0f);
        e4[j4] = o;
        w4[j4] = o;
    }
}

// Fused GEMM2 + softmax + fingerprint accumulation.
// 384 threads = 12 warps; each warp handles NPW=4 nodes, holding all 1024
// logits per node as 16 packed f32x2 per lane (bin = g*128 + lane*4 + c).
// Wo streamed through smem in 16-row chunks; each LDS.128 feeds 8 FFMA2.
__global__ void __launch_bounds__(FB_THREADS, 1)
fused_kernel(const float* __restrict__ Wo, const float* __restrict__ bo, int l) {
    __shared__ float Wos[16 * L_DIM];        // 64 KB
    __shared__ float rs[NPB * F_DIM];        // 12 KB
    __shared__ float fpart[L_DIM];           // 4 KB

    int t = threadIdx.x;
    int w = t >> 5;
    int lane = t & 31;
    int nodeBase = blockIdx.x * NPB + w * NPW;

    for (int i = t; i < L_DIM; i += FB_THREADS) fpart[i] = 0.0f;
    {
        const float4* e4 = (const float4*)g_e;
        float4* rs4 = (float4*)rs;
        for (int i = t; i < NPB * 16; i += FB_THREADS) {
            int node = blockIdx.x * NPB + (i >> 4);
            if (node < N_NODES) rs4[i] = e4[node * 16 + (i & 15)];
            else                rs4[i] = make_float4(0.f, 0.f, 0.f, 0.f);
        }
    }

    // acc[n*16 + g*2 + h] holds bins (g*128 + lane*4 + 2h, +2h+1) of node n
    unsigned long long acc[NPW * 16];
    {
        const float4* bo4 = (const float4*)(bo + l * L_DIM);
#pragma unroll
        for (int g = 0; g < 8; g++) {
            float4 b = bo4[g * 32 + lane];
            unsigned long long b01 = pack2(b.x, b.y);
            unsigned long long b23 = pack2(b.z, b.w);
#pragma unroll
            for (int n = 0; n < NPW; n++) {
                acc[n * 16 + g * 2]     = b01;
                acc[n * 16 + g * 2 + 1] = b23;
            }
        }
    }

    const float4* Wo4 = (const float4*)(Wo + l * F_DIM * L_DIM);
    float4* Wos4 = (float4*)Wos;

    for (int kc = 0; kc < 4; kc++) {
        __syncthreads();
        for (int i = t; i < 4096; i += FB_THREADS) Wos4[i] = Wo4[kc * 4096 + i];
        __syncthreads();
#pragma unroll
        for (int kk = 0; kk < 16; kk++) {
            unsigned long long rk[NPW];
#pragma unroll
            for (int n = 0; n < NPW; n++) {
                float r = rs[(w * NPW + n) * F_DIM + kc * 16 + kk];
                rk[n] = pack2(r, r);
            }
#pragma unroll
            for (int g = 0; g < 8; g++) {
                float4 wv = Wos4[kk * 256 + g * 32 + lane];
                unsigned long long w01 = pack2(wv.x, wv.y);
                unsigned long long w23 = pack2(wv.z, wv.w);
#pragma unroll
                for (int n = 0; n < NPW; n++) {
                    fma2(acc[n * 16 + g * 2],     rk[n], w01);
                    fma2(acc[n * 16 + g * 2 + 1], rk[n], w23);
                }
            }
        }
    }

    // per-node softmax (warp-wide over 1024 bins); accumulate probs of the
    // warp's 4 nodes into p[] in registers, one atomic pass at the end.
    float p[32];
#pragma unroll
    for (int j = 0; j < 32; j++) p[j] = 0.0f;

#pragma unroll
    for (int n = 0; n < NPW; n++) {
        int node = nodeBase + n;
        if (node < N_NODES) {
            // pass 1: max
            float mx = -1e30f;
#pragma unroll
            for (int i = 0; i < 16; i++) {
                float a, b; unpack2(acc[n * 16 + i], a, b);
                mx = fmaxf(mx, fmaxf(a, b));
            }
#pragma unroll
            for (int off = 16; off; off >>= 1)
                mx = fmaxf(mx, __shfl_xor_sync(0xffffffffu, mx, off));
            // pass 2: exp + sum
            float ex[32];
            float sum = 0.0f;
#pragma unroll
            for (int i = 0; i < 16; i++) {
                float a, b; unpack2(acc[n * 16 + i], a, b);
                ex[2 * i]     = __expf(a - mx);
                ex[2 * i + 1] = __expf(b - mx);
                sum += ex[2 * i] + ex[2 * i + 1];
            }
#pragma unroll
            for (int off = 16; off; off >>= 1)
                sum += __shfl_xor_sync(0xffffffffu, sum, off);
            float inv = 1.0f / sum;
#pragma unroll
            for (int j = 0; j < 32; j++) p[j] += ex[j] * inv;
        }
    }

    // p[j] belongs to bin (j>>2)*128 + lane*4 + (j&3)   (j = 4g + 2h + half)
#pragma unroll
    for (int j = 0; j < 32; j++)
        atomicAdd(&fpart[(j >> 2) * 128 + lane * 4 + (j & 3)], p[j]);

    __syncthreads();
    if (t < 256) red_add_v4(g_f + t * 4, ((float4*)fpart)[t]);
}

// out = log_softmax(f @ Wcl + bcl)
__global__ void classify_kernel(const float* __restrict__ Wcl,
                                const float* __restrict__ bcl, float* __restrict__ out) {
    int t = threadIdx.x;
    int lane = t & 31, w = t >> 5;
    float loc[N_CLASS];
#pragma unroll
    for (int c = 0; c < N_CLASS; c++) loc[c] = 0.0f;
    for (int i = t; i < L_DIM; i += 256) {
        float fv = g_f[i];
#pragma unroll
        for (int c = 0; c < N_CLASS; c++) loc[c] += fv * Wcl[i * N_CLASS + c];
    }
#pragma unroll
    for (int c = 0; c < N_CLASS; c++)
#pragma unroll
        for (int off = 16; off; off >>= 1)
            loc[c] += __shfl_xor_sync(0xffffffffu, loc[c], off);

    __shared__ float ws[8][N_CLASS];
    if (lane == 0)
#pragma unroll
        for (int c = 0; c < N_CLASS; c++) ws[w][c] = loc[c];
    __syncthreads();
    if (t == 0) {
        float z[N_CLASS];
#pragma unroll
        for (int c = 0; c < N_CLASS; c++) {
            z[c] = bcl[c];
            for (int k = 0; k < 8; k++) z[c] += ws[k][c];
        }
        float m = z[0];
#pragma unroll
        for (int c = 1; c < N_CLASS; c++) m = fmaxf(m, z[c]);
        float s = 0.0f;
#pragma unroll
        for (int c = 0; c < N_CLASS; c++) s += __expf(z[c] - m);
        float ls = logf(s);
#pragma unroll
        for (int c = 0; c < N_CLASS; c++) out[c] = z[c] - m - ls;
    }
}

extern "C" void kernel_launch(void* const* d_in, const int* in_sizes, int n_in,
                              void* d_out, int out_size) {
    const int*   nf   = (const int*)  d_in[0];
    const int*   esrc = (const int*)  d_in[1];
    const int*   edst = (const int*)  d_in[2];
    const float* emb  = (const float*)d_in[3];
    const float* Wh   = (const float*)d_in[4];
    const float* bh   = (const float*)d_in[5];
    const float* Wo   = (const float*)d_in[6];
    const float* bo   = (const float*)d_in[7];
    const float* Wcl  = (const float*)d_in[8];
    const float* bcl  = (const float*)d_in[9];
    float* out = (float*)d_out;

    gather_init<<<(N_NODES * 16 + 255) / 256, 256>>>(nf, emb);
    for (int l = 0; l < R_ROUNDS; l++) {
        scatter_kernel<<<(N_EDGES * 16 + 255) / 256, 256>>>(esrc, edst);
        gemm1_kernel<<<(N_NODES + 255) / 256, 256>>>(Wh, bh, l);
        fused_kernel<<<(N_NODES + NPB - 1) / NPB, FB_THREADS>>>(Wo, bo, l);
    }
    classify_kernel<<<1, 256>>>(Wcl, bcl, out);
}